// round 14
// baseline (speedup 1.0000x reference)
#include <cuda_runtime.h>
#include <cuda_fp16.h>
#include <stdint.h>

#define TOKENS   65536
#define KD       512
#define NC1      1536
#define NHEADS   16
#define SCALE_Q  0.17677669529663688f

// ------------------------- device scratch (static) -------------------------
__device__ __half   g_q_h  [TOKENS * KD];
__device__ __half   g_w1_h [KD * NC1];
__device__ __half   g_w3_h [KD * KD];
__device__ __half   g_qkv_h[(size_t)TOKENS * NC1];
__device__ __half   g_o_h  [TOKENS * KD];
__device__ uint8_t  g_idx8 [4096];

// ------------------------------ PTX helpers --------------------------------
__device__ __forceinline__ uint32_t smem_u32(const void* p) {
    return (uint32_t)__cvta_generic_to_shared(p);
}
__device__ __forceinline__ void cp16(void* s, const void* g) {
    asm volatile("cp.async.cg.shared.global [%0], [%1], 16;\n"
                 :: "r"(smem_u32(s)), "l"(g));
}
__device__ __forceinline__ void cp_commit() { asm volatile("cp.async.commit_group;\n"); }
template<int N> __device__ __forceinline__ void cp_wait() {
    asm volatile("cp.async.wait_group %0;\n" :: "n"(N));
}
__device__ __forceinline__ void ldsm4(uint32_t r[4], const void* p) {
    asm volatile("ldmatrix.sync.aligned.m8n8.x4.shared.b16 {%0,%1,%2,%3}, [%4];\n"
        : "=r"(r[0]), "=r"(r[1]), "=r"(r[2]), "=r"(r[3]) : "r"(smem_u32(p)));
}
__device__ __forceinline__ void ldsm4t(uint32_t r[4], const void* p) {
    asm volatile("ldmatrix.sync.aligned.m8n8.x4.trans.shared.b16 {%0,%1,%2,%3}, [%4];\n"
        : "=r"(r[0]), "=r"(r[1]), "=r"(r[2]), "=r"(r[3]) : "r"(smem_u32(p)));
}
__device__ __forceinline__ void mma_f16(float c[4], const uint32_t a[4], const uint32_t b[2]) {
    asm volatile(
        "mma.sync.aligned.m16n8k16.row.col.f32.f16.f16.f32 "
        "{%0,%1,%2,%3}, {%4,%5,%6,%7}, {%8,%9}, {%0,%1,%2,%3};\n"
        : "+f"(c[0]), "+f"(c[1]), "+f"(c[2]), "+f"(c[3])
        : "r"(a[0]), "r"(a[1]), "r"(a[2]), "r"(a[3]), "r"(b[0]), "r"(b[1]));
}
__device__ __forceinline__ uint32_t pack_h2(float a, float b) {
    __half2 h = __floats2half2_rn(a, b);
    return *reinterpret_cast<uint32_t*>(&h);
}
__device__ __forceinline__ void st_cs_f2(float* p, float a, float b) {
    asm volatile("st.global.cs.v2.f32 [%0], {%1, %2};"
                 :: "l"(p), "f"(a), "f"(b) : "memory");
}

// ------------------------------ prep kernels -------------------------------
__global__ void to_half4_kernel(const float4* __restrict__ src,
                                uint2* __restrict__ dst, int n4) {
    int i = blockIdx.x * blockDim.x + threadIdx.x;
    if (i >= n4) return;
    float4 v = src[i];
    dst[i] = make_uint2(pack_h2(v.x, v.y), pack_h2(v.z, v.w));
}

__global__ void w1_half_kernel(const float* __restrict__ wq,
                               const float* __restrict__ wkv,
                               const int* __restrict__ relidx) {
    int i = blockIdx.x * blockDim.x + threadIdx.x;
    if (i >= KD * NC1) return;
    int k = i / NC1, n = i - k * NC1;
    float v = (n < KD) ? wq[k * KD + n] : wkv[k * 1024 + (n - KD)];
    g_w1_h[i] = __float2half(v);
    if (i < 4096) g_idx8[i] = (uint8_t)relidx[i];
}

// ------ single-pass fp16 GEMM, 128x128x32 tiles, 4 warps @ m64n64 ----------
// (R12 configuration — best known, frozen.)  C = A_fp16 * B_fp16.
// MODE 1: QKV epilogue (bias + Q scale, fp16 out). MODE 3: fp32 out + bias.
template<int NCOLS, int MODE>
__global__ __launch_bounds__(128, 2)
void gemm_kernel(const __half* __restrict__ A, const __half* __restrict__ B,
                 const float* __restrict__ bias0, const float* __restrict__ bias1,
                 __half* __restrict__ outh, float* __restrict__ outf)
{
    constexpr int SA = 40;
    constexpr int SB = 136;
    constexpr int NB = NCOLS / 128;
    constexpr int GROUP_M = 16;
    constexpr int STAGE = 128 * SA + 32 * SB;   // 9472 halfs / stage
    constexpr int KITER = KD / 32;              // 16

    extern __shared__ char smem_raw[];
    __half* smem = (__half*)smem_raw;

    int bid = blockIdx.x;
    int gsz = GROUP_M * NB;
    int grp = bid / gsz;
    int rem = bid - grp * gsz;
    int bm  = grp * GROUP_M + (rem % GROUP_M);
    int bn  = rem / GROUP_M;

    int tid = threadIdx.x, lane = tid & 31, wid = tid >> 5;
    int wm = wid & 1, wn = wid >> 1;
    const int arow = tid >> 2, acol8 = (tid & 3) * 8;
    const int brow = tid >> 4, bcol8 = (tid & 15) * 8;

    auto load_stage = [&](__half* sb, int k0) {
        __half* dA = sb;
        __half* dB = sb + 128 * SA;
        #pragma unroll
        for (int i = 0; i < 4; i++) {
            size_t ga = (size_t)(bm * 128 + arow + 32 * i) * KD + k0 + acol8;
            cp16(dA + (arow + 32 * i) * SA + acol8, A + ga);
        }
        #pragma unroll
        for (int i = 0; i < 4; i++) {
            size_t gb = (size_t)(k0 + brow + 8 * i) * NCOLS + bn * 128 + bcol8;
            cp16(dB + (brow + 8 * i) * SB + bcol8, B + gb);
        }
    };

    float acc[4][8][4];
    #pragma unroll
    for (int a = 0; a < 4; a++)
        #pragma unroll
        for (int b = 0; b < 8; b++)
            #pragma unroll
            for (int c = 0; c < 4; c++) acc[a][b][c] = 0.f;

    __half* bc  = smem;
    __half* bnx = smem + STAGE;
    __half* blw = smem + 2 * STAGE;

    load_stage(bc, 0);
    cp_commit();
    load_stage(bnx, 32);
    cp_commit();

    #pragma unroll 1
    for (int kt = 0; kt < KITER; kt++) {
        cp_wait<1>();
        __syncthreads();
        if (kt + 2 < KITER) load_stage(blw, (kt + 2) * 32);
        cp_commit();

        const __half* cA = bc;
        const __half* cB = bc + 128 * SA;

        #pragma unroll
        for (int kk = 0; kk < 2; kk++) {
            uint32_t a[4][4], b[4][4];
            int ac = kk * 16 + (lane >> 4) * 8;
            int br = kk * 16 + (lane & 15);
            #pragma unroll
            for (int mt = 0; mt < 4; mt++) {
                int ar = wm * 64 + mt * 16 + (lane & 15);
                ldsm4(a[mt], cA + ar * SA + ac);
            }
            #pragma unroll
            for (int nj2 = 0; nj2 < 4; nj2++) {
                int bcc = wn * 64 + nj2 * 16 + (lane >> 4) * 8;
                ldsm4t(b[nj2], cB + br * SB + bcc);
            }
            #pragma unroll
            for (int nj2 = 0; nj2 < 4; nj2++) {
                #pragma unroll
                for (int t = 0; t < 2; t++) {
                    int nj = nj2 * 2 + t;
                    #pragma unroll
                    for (int mt = 0; mt < 4; mt++)
                        mma_f16(acc[mt][nj], a[mt], b[nj2] + 2 * t);
                }
            }
        }
        __half* tmp = bc;
        bc = bnx; bnx = blw; blw = tmp;
    }

    int row0 = bm * 128 + wm * 64 + (lane >> 2);
    int col0 = bn * 128 + wn * 64 + (lane & 3) * 2;
    #pragma unroll
    for (int mi = 0; mi < 4; mi++) {
        int ra = row0 + mi * 16;
        #pragma unroll
        for (int nj = 0; nj < 8; nj++) {
            int col = col0 + nj * 8;
            if (MODE == 1) {
                float b0, b1; float sc0, sc1;
                if (col < 512) { b0 = bias0[col]; b1 = bias0[col + 1]; sc0 = SCALE_Q; sc1 = SCALE_Q; }
                else { b0 = bias1[col - 512]; b1 = bias1[col - 511]; sc0 = 1.f; sc1 = 1.f; }
                size_t g0 = (size_t)ra * NCOLS + col;
                *(__half2*)&outh[g0] = __floats2half2_rn(
                    (acc[mi][nj][0] + b0) * sc0, (acc[mi][nj][1] + b1) * sc1);
                size_t g1 = (size_t)(ra + 8) * NCOLS + col;
                *(__half2*)&outh[g1] = __floats2half2_rn(
                    (acc[mi][nj][2] + b0) * sc0, (acc[mi][nj][3] + b1) * sc1);
            } else {
                float b0 = bias0[col], b1 = bias0[col + 1];
                st_cs_f2(&outf[(size_t)ra * NCOLS + col],
                         acc[mi][nj][0] + b0, acc[mi][nj][1] + b1);
                st_cs_f2(&outf[(size_t)(ra + 8) * NCOLS + col],
                         acc[mi][nj][2] + b0, acc[mi][nj][3] + b1);
            }
        }
    }
}

// ------------- tensor-core attention: 2 heads / CTA, 8 warps ---------------
// Warps 0-3 -> head 2hp, warps 4-7 -> head 2hp+1. launch_bounds(256,3) caps
// regs at 85 to lift residency from 2 to 3 CTAs/SM (wave count 27 -> 18).
__global__ __launch_bounds__(256, 3)
void attn_mma_kernel(const __half* __restrict__ qkvh,
                     const float* __restrict__ table,
                     const uint8_t* __restrict__ idx8,
                     float* __restrict__ attn_out,
                     __half* __restrict__ oh)
{
    constexpr int SQ2 = 72;                    // 64 + 8 pad
    extern __shared__ char smraw[];
    __half* sT = (__half*)smraw;                       // 3 x [64*SQ2] : Q K V (both heads)
    float*   sTab = (float*)(smraw + 3 * 64 * SQ2 * 2);  // [2][228]
    uint8_t* sIdx = (uint8_t*)(sTab + 2 * 228);          // 4096 B

    const int w = blockIdx.x >> 3, hp = blockIdx.x & 7;
    const int tid = threadIdx.x, lane = tid & 31, wid = tid >> 5;
    const int hsel = wid >> 2, wr = wid & 3;
    const int h = hp * 2 + hsel;
    const int hc = hsel * 32;
    const size_t rowbase = (size_t)(w * 64) * NC1;

    #pragma unroll
    for (int it = 0; it < 6; it++) {
        int e = tid + it * 256;
        int a = e >> 9;
        int rem = e & 511;
        int row = rem >> 3, c = (rem & 7) * 8;
        size_t g = rowbase + (size_t)row * NC1 + hp * 64 + a * 512 + c;
        cp16(sT + a * (64 * SQ2) + row * SQ2 + c, qkvh + g);
    }
    cp16(sIdx + tid * 16, idx8 + tid * 16);
    cp_commit();
    for (int t = tid; t < 225; t += 256) {
        sTab[t]       = table[t * NHEADS + hp * 2];
        sTab[228 + t] = table[t * NHEADS + hp * 2 + 1];
    }
    cp_wait<0>();
    __syncthreads();

    const __half* sQh = sT;
    const __half* sKh = sT + 1 * (64 * SQ2);
    const __half* sVh = sT + 2 * (64 * SQ2);
    const float*  sTabH = sTab + hsel * 228;

    const int r0 = wr * 16;

    uint32_t qa[2][4];
    #pragma unroll
    for (int kc = 0; kc < 2; kc++) {
        int ad = (r0 + (lane & 15)) * SQ2 + hc + kc * 16 + (lane >> 4) * 8;
        ldsm4(qa[kc], sQh + ad);
    }
    float acc[8][4];
    #pragma unroll
    for (int j = 0; j < 8; j++)
        #pragma unroll
        for (int c = 0; c < 4; c++) acc[j][c] = 0.f;

    #pragma unroll
    for (int kc = 0; kc < 2; kc++) {
        #pragma unroll
        for (int jj = 0; jj < 4; jj++) {
            int row = jj * 16 + (lane & 7) + ((lane >> 4) & 1) * 8;
            int col = hc + kc * 16 + ((lane >> 3) & 1) * 8;
            uint32_t kh[4];
            ldsm4(kh, sKh + row * SQ2 + col);
            mma_f16(acc[2 * jj],     qa[kc], kh);
            mma_f16(acc[2 * jj + 1], qa[kc], kh + 2);
        }
    }

    const int rA = r0 + (lane >> 2), rB = rA + 8;
    const int cb = (lane & 3) * 2;
    float mA = -1e30f, mB = -1e30f;
    #pragma unroll
    for (int j = 0; j < 8; j++) {
        int c0 = j * 8 + cb;
        acc[j][0] += sTabH[sIdx[rA * 64 + c0]];
        acc[j][1] += sTabH[sIdx[rA * 64 + c0 + 1]];
        acc[j][2] += sTabH[sIdx[rB * 64 + c0]];
        acc[j][3] += sTabH[sIdx[rB * 64 + c0 + 1]];
        mA = fmaxf(mA, fmaxf(acc[j][0], acc[j][1]));
        mB = fmaxf(mB, fmaxf(acc[j][2], acc[j][3]));
    }
    mA = fmaxf(mA, __shfl_xor_sync(0xffffffffu, mA, 1));
    mA = fmaxf(mA, __shfl_xor_sync(0xffffffffu, mA, 2));
    mB = fmaxf(mB, __shfl_xor_sync(0xffffffffu, mB, 1));
    mB = fmaxf(mB, __shfl_xor_sync(0xffffffffu, mB, 2));
    float sA = 0.f, sB = 0.f;
    #pragma unroll
    for (int j = 0; j < 8; j++) {
        acc[j][0] = __expf(acc[j][0] - mA);
        acc[j][1] = __expf(acc[j][1] - mA);
        acc[j][2] = __expf(acc[j][2] - mB);
        acc[j][3] = __expf(acc[j][3] - mB);
        sA += acc[j][0] + acc[j][1];
        sB += acc[j][2] + acc[j][3];
    }
    sA += __shfl_xor_sync(0xffffffffu, sA, 1);
    sA += __shfl_xor_sync(0xffffffffu, sA, 2);
    sB += __shfl_xor_sync(0xffffffffu, sB, 1);
    sB += __shfl_xor_sync(0xffffffffu, sB, 2);
    const float invA = 1.f / sA, invB = 1.f / sB;

    uint32_t pa[4][4];
    const size_t abase = ((size_t)w * NHEADS + h) * 64;
    #pragma unroll
    for (int j = 0; j < 8; j++) {
        float p0 = acc[j][0] * invA, p1 = acc[j][1] * invA;
        float p2 = acc[j][2] * invB, p3 = acc[j][3] * invB;
        st_cs_f2(&attn_out[(abase + rA) * 64 + j * 8 + cb], p0, p1);
        st_cs_f2(&attn_out[(abase + rB) * 64 + j * 8 + cb], p2, p3);
        int t = j >> 1, s = (j & 1) * 2;
        pa[t][s + 0] = pack_h2(p0, p1);
        pa[t][s + 1] = pack_h2(p2, p3);
    }

    float o[4][4];
    #pragma unroll
    for (int nj = 0; nj < 4; nj++)
        #pragma unroll
        for (int c = 0; c < 4; c++) o[nj][c] = 0.f;
    #pragma unroll
    for (int kc = 0; kc < 4; kc++) {
        #pragma unroll
        for (int vb = 0; vb < 2; vb++) {
            int ad = (kc * 16 + (lane & 15)) * SQ2 + hc + vb * 16 + (lane >> 4) * 8;
            uint32_t vh[4];
            ldsm4t(vh, sVh + ad);
            mma_f16(o[vb * 2],     pa[kc], vh);
            mma_f16(o[vb * 2 + 1], pa[kc], vh + 2);
        }
    }

    #pragma unroll
    for (int nj = 0; nj < 4; nj++) {
        int col = h * 32 + nj * 8 + cb;
        size_t gA = (size_t)(w * 64 + rA) * KD + col;
        size_t gB = (size_t)(w * 64 + rB) * KD + col;
        *(__half2*)&oh[gA] = __floats2half2_rn(o[nj][0], o[nj][1]);
        *(__half2*)&oh[gB] = __floats2half2_rn(o[nj][2], o[nj][3]);
    }
}

// ------------------------------- launcher ----------------------------------
extern "C" void kernel_launch(void* const* d_in, const int* in_sizes, int n_in,
                              void* d_out, int out_size) {
    const float* q      = (const float*)d_in[0];
    const float* wq     = (const float*)d_in[1];
    const float* bq     = (const float*)d_in[2];
    const float* wkv    = (const float*)d_in[3];
    const float* bkv    = (const float*)d_in[4];
    const float* wproj  = (const float*)d_in[5];
    const float* bproj  = (const float*)d_in[6];
    const float* table  = (const float*)d_in[7];
    const int*   relidx = (const int*)d_in[8];

    float* out_x    = (float*)d_out;
    float* out_attn = out_x + (size_t)TOKENS * KD;

    __half *q_h, *w1_h, *w3_h, *qkv_h, *o_h;
    uint8_t* idx8;
    cudaGetSymbolAddress((void**)&q_h,   g_q_h);
    cudaGetSymbolAddress((void**)&w1_h,  g_w1_h);
    cudaGetSymbolAddress((void**)&w3_h,  g_w3_h);
    cudaGetSymbolAddress((void**)&qkv_h, g_qkv_h);
    cudaGetSymbolAddress((void**)&o_h,   g_o_h);
    cudaGetSymbolAddress((void**)&idx8,  g_idx8);

    const int smem_gemm = 3 * (128 * 40 + 32 * 136) * 2;          // 56,832
    const int smem_attn = 3 * 64 * 72 * 2 + 2 * 228 * 4 + 4096;   // 33,568
    cudaFuncSetAttribute(gemm_kernel<NC1, 1>, cudaFuncAttributeMaxDynamicSharedMemorySize, smem_gemm);
    cudaFuncSetAttribute(gemm_kernel<KD, 3>,  cudaFuncAttributeMaxDynamicSharedMemorySize, smem_gemm);
    cudaFuncSetAttribute(attn_mma_kernel, cudaFuncAttributeMaxDynamicSharedMemorySize, smem_attn);

    to_half4_kernel<<<(TOKENS * KD / 4 + 255) / 256, 256>>>(
        (const float4*)q, (uint2*)q_h, TOKENS * KD / 4);
    w1_half_kernel<<<(KD * NC1) / 256, 256>>>(wq, wkv, relidx);
    to_half4_kernel<<<(KD * KD / 4 + 255) / 256, 256>>>(
        (const float4*)wproj, (uint2*)w3_h, KD * KD / 4);

    gemm_kernel<NC1, 1><<<(TOKENS / 128) * (NC1 / 128), 128, smem_gemm>>>(
        q_h, w1_h, bq, bkv, qkv_h, nullptr);

    attn_mma_kernel<<<1024 * 8, 256, smem_attn>>>(
        qkv_h, table, idx8, out_attn, o_h);

    gemm_kernel<KD, 3><<<(TOKENS / 128) * (KD / 128), 128, smem_gemm>>>(
        o_h, w3_h, bproj, nullptr, nullptr, out_x);
}

// round 15
// speedup vs baseline: 1.0047x; 1.0047x over previous
#include <cuda_runtime.h>
#include <cuda_fp16.h>
#include <stdint.h>

#define TOKENS   65536
#define KD       512
#define NC1      1536
#define NHEADS   16
#define SCALE_Q  0.17677669529663688f

// ------------------------- device scratch (static) -------------------------
__device__ __half   g_q_h  [TOKENS * KD];
__device__ __half   g_w1_h [KD * NC1];
__device__ __half   g_w3_h [KD * KD];
__device__ __half   g_qkv_h[(size_t)TOKENS * NC1];
__device__ __half   g_o_h  [TOKENS * KD];
__device__ uint8_t  g_idx8 [4096];

// ------------------------------ PTX helpers --------------------------------
__device__ __forceinline__ uint32_t smem_u32(const void* p) {
    return (uint32_t)__cvta_generic_to_shared(p);
}
__device__ __forceinline__ void cp16(void* s, const void* g) {
    asm volatile("cp.async.cg.shared.global [%0], [%1], 16;\n"
                 :: "r"(smem_u32(s)), "l"(g));
}
__device__ __forceinline__ void cp_commit() { asm volatile("cp.async.commit_group;\n"); }
template<int N> __device__ __forceinline__ void cp_wait() {
    asm volatile("cp.async.wait_group %0;\n" :: "n"(N));
}
__device__ __forceinline__ void ldsm4(uint32_t r[4], const void* p) {
    asm volatile("ldmatrix.sync.aligned.m8n8.x4.shared.b16 {%0,%1,%2,%3}, [%4];\n"
        : "=r"(r[0]), "=r"(r[1]), "=r"(r[2]), "=r"(r[3]) : "r"(smem_u32(p)));
}
__device__ __forceinline__ void ldsm4t(uint32_t r[4], const void* p) {
    asm volatile("ldmatrix.sync.aligned.m8n8.x4.trans.shared.b16 {%0,%1,%2,%3}, [%4];\n"
        : "=r"(r[0]), "=r"(r[1]), "=r"(r[2]), "=r"(r[3]) : "r"(smem_u32(p)));
}
__device__ __forceinline__ void mma_f16(float c[4], const uint32_t a[4], const uint32_t b[2]) {
    asm volatile(
        "mma.sync.aligned.m16n8k16.row.col.f32.f16.f16.f32 "
        "{%0,%1,%2,%3}, {%4,%5,%6,%7}, {%8,%9}, {%0,%1,%2,%3};\n"
        : "+f"(c[0]), "+f"(c[1]), "+f"(c[2]), "+f"(c[3])
        : "r"(a[0]), "r"(a[1]), "r"(a[2]), "r"(a[3]), "r"(b[0]), "r"(b[1]));
}
__device__ __forceinline__ uint32_t pack_h2(float a, float b) {
    __half2 h = __floats2half2_rn(a, b);
    return *reinterpret_cast<uint32_t*>(&h);
}
__device__ __forceinline__ void st_cs_f2(float* p, float a, float b) {
    asm volatile("st.global.cs.v2.f32 [%0], {%1, %2};"
                 :: "l"(p), "f"(a), "f"(b) : "memory");
}

// ------------------------------ prep kernels -------------------------------
__global__ void to_half4_kernel(const float4* __restrict__ src,
                                uint2* __restrict__ dst, int n4) {
    int i = blockIdx.x * blockDim.x + threadIdx.x;
    if (i >= n4) return;
    float4 v = src[i];
    dst[i] = make_uint2(pack_h2(v.x, v.y), pack_h2(v.z, v.w));
}

// w1 (concat+convert), w3 (convert), idx8 (pack) in one launch
__global__ void prep_weights_kernel(const float* __restrict__ wq,
                                    const float* __restrict__ wkv,
                                    const float* __restrict__ wproj,
                                    const int* __restrict__ relidx) {
    int i = blockIdx.x * blockDim.x + threadIdx.x;
    if (i < KD * NC1) {
        int k = i / NC1, n = i - k * NC1;
        float v = (n < KD) ? wq[k * KD + n] : wkv[k * 1024 + (n - KD)];
        g_w1_h[i] = __float2half(v);
    }
    if (i < KD * KD) g_w3_h[i] = __float2half(wproj[i]);
    if (i < 4096)    g_idx8[i] = (uint8_t)relidx[i];
}

// ------ single-pass fp16 GEMM, 128x128x32 tiles, 4 warps @ m64n64 ----------
// (R12 configuration — best known, frozen.)  C = A_fp16 * B_fp16.
// MODE 1: QKV epilogue (bias + Q scale, fp16 out). MODE 3: fp32 out + bias.
template<int NCOLS, int MODE>
__global__ __launch_bounds__(128, 2)
void gemm_kernel(const __half* __restrict__ A, const __half* __restrict__ B,
                 const float* __restrict__ bias0, const float* __restrict__ bias1,
                 __half* __restrict__ outh, float* __restrict__ outf)
{
    constexpr int SA = 40;
    constexpr int SB = 136;
    constexpr int NB = NCOLS / 128;
    constexpr int GROUP_M = 16;
    constexpr int STAGE = 128 * SA + 32 * SB;   // 9472 halfs / stage
    constexpr int KITER = KD / 32;              // 16

    extern __shared__ char smem_raw[];
    __half* smem = (__half*)smem_raw;

    int bid = blockIdx.x;
    int gsz = GROUP_M * NB;
    int grp = bid / gsz;
    int rem = bid - grp * gsz;
    int bm  = grp * GROUP_M + (rem % GROUP_M);
    int bn  = rem / GROUP_M;

    int tid = threadIdx.x, lane = tid & 31, wid = tid >> 5;
    int wm = wid & 1, wn = wid >> 1;
    const int arow = tid >> 2, acol8 = (tid & 3) * 8;
    const int brow = tid >> 4, bcol8 = (tid & 15) * 8;

    auto load_stage = [&](__half* sb, int k0) {
        __half* dA = sb;
        __half* dB = sb + 128 * SA;
        #pragma unroll
        for (int i = 0; i < 4; i++) {
            size_t ga = (size_t)(bm * 128 + arow + 32 * i) * KD + k0 + acol8;
            cp16(dA + (arow + 32 * i) * SA + acol8, A + ga);
        }
        #pragma unroll
        for (int i = 0; i < 4; i++) {
            size_t gb = (size_t)(k0 + brow + 8 * i) * NCOLS + bn * 128 + bcol8;
            cp16(dB + (brow + 8 * i) * SB + bcol8, B + gb);
        }
    };

    float acc[4][8][4];
    #pragma unroll
    for (int a = 0; a < 4; a++)
        #pragma unroll
        for (int b = 0; b < 8; b++)
            #pragma unroll
            for (int c = 0; c < 4; c++) acc[a][b][c] = 0.f;

    __half* bc  = smem;
    __half* bnx = smem + STAGE;
    __half* blw = smem + 2 * STAGE;

    load_stage(bc, 0);
    cp_commit();
    load_stage(bnx, 32);
    cp_commit();

    #pragma unroll 1
    for (int kt = 0; kt < KITER; kt++) {
        cp_wait<1>();
        __syncthreads();
        if (kt + 2 < KITER) load_stage(blw, (kt + 2) * 32);
        cp_commit();

        const __half* cA = bc;
        const __half* cB = bc + 128 * SA;

        #pragma unroll
        for (int kk = 0; kk < 2; kk++) {
            uint32_t a[4][4], b[4][4];
            int ac = kk * 16 + (lane >> 4) * 8;
            int br = kk * 16 + (lane & 15);
            #pragma unroll
            for (int mt = 0; mt < 4; mt++) {
                int ar = wm * 64 + mt * 16 + (lane & 15);
                ldsm4(a[mt], cA + ar * SA + ac);
            }
            #pragma unroll
            for (int nj2 = 0; nj2 < 4; nj2++) {
                int bcc = wn * 64 + nj2 * 16 + (lane >> 4) * 8;
                ldsm4t(b[nj2], cB + br * SB + bcc);
            }
            #pragma unroll
            for (int nj2 = 0; nj2 < 4; nj2++) {
                #pragma unroll
                for (int t = 0; t < 2; t++) {
                    int nj = nj2 * 2 + t;
                    #pragma unroll
                    for (int mt = 0; mt < 4; mt++)
                        mma_f16(acc[mt][nj], a[mt], b[nj2] + 2 * t);
                }
            }
        }
        __half* tmp = bc;
        bc = bnx; bnx = blw; blw = tmp;
    }

    int row0 = bm * 128 + wm * 64 + (lane >> 2);
    int col0 = bn * 128 + wn * 64 + (lane & 3) * 2;
    #pragma unroll
    for (int mi = 0; mi < 4; mi++) {
        int ra = row0 + mi * 16;
        #pragma unroll
        for (int nj = 0; nj < 8; nj++) {
            int col = col0 + nj * 8;
            if (MODE == 1) {
                float b0, b1; float sc0, sc1;
                if (col < 512) { b0 = bias0[col]; b1 = bias0[col + 1]; sc0 = SCALE_Q; sc1 = SCALE_Q; }
                else { b0 = bias1[col - 512]; b1 = bias1[col - 511]; sc0 = 1.f; sc1 = 1.f; }
                size_t g0 = (size_t)ra * NCOLS + col;
                *(__half2*)&outh[g0] = __floats2half2_rn(
                    (acc[mi][nj][0] + b0) * sc0, (acc[mi][nj][1] + b1) * sc1);
                size_t g1 = (size_t)(ra + 8) * NCOLS + col;
                *(__half2*)&outh[g1] = __floats2half2_rn(
                    (acc[mi][nj][2] + b0) * sc0, (acc[mi][nj][3] + b1) * sc1);
            } else {
                float b0 = bias0[col], b1 = bias0[col + 1];
                st_cs_f2(&outf[(size_t)ra * NCOLS + col],
                         acc[mi][nj][0] + b0, acc[mi][nj][1] + b1);
                st_cs_f2(&outf[(size_t)(ra + 8) * NCOLS + col],
                         acc[mi][nj][2] + b0, acc[mi][nj][3] + b1);
            }
        }
    }
}

// ------ tensor-core attention: 2 heads/CTA, 2 tiles/CTA double-buffered ----
// Each CTA processes tiles t = blockIdx*2 and blockIdx*2+1 (tile = (w, hp)).
// Both tile loads issued up front; tile1 loads overlap tile0 compute.
// Per-tile math identical to R13 (bit-identical output).
__global__ __launch_bounds__(256)
void attn_mma_kernel(const __half* __restrict__ qkvh,
                     const float* __restrict__ table,
                     const uint8_t* __restrict__ idx8,
                     float* __restrict__ attn_out,
                     __half* __restrict__ oh)
{
    constexpr int SQ2 = 72;                       // 64 + 8 pad
    constexpr int TILE_H = 3 * 64 * SQ2;          // halfs per stage (Q|K|V)
    extern __shared__ char smraw[];
    __half* sT = (__half*)smraw;                              // 2 stages
    float*   sTab = (float*)(smraw + 2 * TILE_H * 2);         // [2 stg][2 heads][228]
    uint8_t* sIdx = (uint8_t*)(sTab + 4 * 228);               // 4096 B

    const int tid = threadIdx.x, lane = tid & 31, wid = tid >> 5;
    const int hsel = wid >> 2, wr = wid & 3;
    const int hc = hsel * 32;
    const int t0 = blockIdx.x * 2;

    // issue loads for both tiles
    #pragma unroll
    for (int st = 0; st < 2; st++) {
        int t = t0 + st;
        int w = t >> 3, hp = t & 7;
        size_t rowbase = (size_t)(w * 64) * NC1;
        #pragma unroll
        for (int it = 0; it < 6; it++) {
            int e = tid + it * 256;
            int a = e >> 9;
            int rem = e & 511;
            int row = rem >> 3, c = (rem & 7) * 8;
            size_t g = rowbase + (size_t)row * NC1 + hp * 64 + a * 512 + c;
            cp16(sT + st * TILE_H + a * (64 * SQ2) + row * SQ2 + c, qkvh + g);
        }
        if (st == 0) cp16(sIdx + tid * 16, idx8 + tid * 16);
        cp_commit();
    }
    // bias table columns for both stages / both heads (plain loads, small)
    {
        int hpA = t0 & 7, hpB = (t0 + 1) & 7;
        for (int e = tid; e < 225; e += 256) {
            sTab[e]           = table[e * NHEADS + hpA * 2];
            sTab[228 + e]     = table[e * NHEADS + hpA * 2 + 1];
            sTab[456 + e]     = table[e * NHEADS + hpB * 2];
            sTab[684 + e]     = table[e * NHEADS + hpB * 2 + 1];
        }
    }

    #pragma unroll
    for (int st = 0; st < 2; st++) {
        if (st == 0) cp_wait<1>();
        else         cp_wait<0>();
        __syncthreads();

        const int t = t0 + st;
        const int w = t >> 3, hp = t & 7;
        const int h = hp * 2 + hsel;
        const __half* sQh = sT + st * TILE_H;
        const __half* sKh = sQh + 1 * (64 * SQ2);
        const __half* sVh = sQh + 2 * (64 * SQ2);
        const float*  sTabH = sTab + (st * 2 + hsel) * 228;

        const int r0 = wr * 16;

        uint32_t qa[2][4];
        #pragma unroll
        for (int kc = 0; kc < 2; kc++) {
            int ad = (r0 + (lane & 15)) * SQ2 + hc + kc * 16 + (lane >> 4) * 8;
            ldsm4(qa[kc], sQh + ad);
        }
        float acc[8][4];
        #pragma unroll
        for (int j = 0; j < 8; j++)
            #pragma unroll
            for (int c = 0; c < 4; c++) acc[j][c] = 0.f;

        #pragma unroll
        for (int kc = 0; kc < 2; kc++) {
            #pragma unroll
            for (int jj = 0; jj < 4; jj++) {
                int row = jj * 16 + (lane & 7) + ((lane >> 4) & 1) * 8;
                int col = hc + kc * 16 + ((lane >> 3) & 1) * 8;
                uint32_t kh[4];
                ldsm4(kh, sKh + row * SQ2 + col);
                mma_f16(acc[2 * jj],     qa[kc], kh);
                mma_f16(acc[2 * jj + 1], qa[kc], kh + 2);
            }
        }

        const int rA = r0 + (lane >> 2), rB = rA + 8;
        const int cb = (lane & 3) * 2;
        float mA = -1e30f, mB = -1e30f;
        #pragma unroll
        for (int j = 0; j < 8; j++) {
            int c0 = j * 8 + cb;
            acc[j][0] += sTabH[sIdx[rA * 64 + c0]];
            acc[j][1] += sTabH[sIdx[rA * 64 + c0 + 1]];
            acc[j][2] += sTabH[sIdx[rB * 64 + c0]];
            acc[j][3] += sTabH[sIdx[rB * 64 + c0 + 1]];
            mA = fmaxf(mA, fmaxf(acc[j][0], acc[j][1]));
            mB = fmaxf(mB, fmaxf(acc[j][2], acc[j][3]));
        }
        mA = fmaxf(mA, __shfl_xor_sync(0xffffffffu, mA, 1));
        mA = fmaxf(mA, __shfl_xor_sync(0xffffffffu, mA, 2));
        mB = fmaxf(mB, __shfl_xor_sync(0xffffffffu, mB, 1));
        mB = fmaxf(mB, __shfl_xor_sync(0xffffffffu, mB, 2));
        float sA = 0.f, sB = 0.f;
        #pragma unroll
        for (int j = 0; j < 8; j++) {
            acc[j][0] = __expf(acc[j][0] - mA);
            acc[j][1] = __expf(acc[j][1] - mA);
            acc[j][2] = __expf(acc[j][2] - mB);
            acc[j][3] = __expf(acc[j][3] - mB);
            sA += acc[j][0] + acc[j][1];
            sB += acc[j][2] + acc[j][3];
        }
        sA += __shfl_xor_sync(0xffffffffu, sA, 1);
        sA += __shfl_xor_sync(0xffffffffu, sA, 2);
        sB += __shfl_xor_sync(0xffffffffu, sB, 1);
        sB += __shfl_xor_sync(0xffffffffu, sB, 2);
        const float invA = 1.f / sA, invB = 1.f / sB;

        uint32_t pa[4][4];
        const size_t abase = ((size_t)w * NHEADS + h) * 64;
        #pragma unroll
        for (int j = 0; j < 8; j++) {
            float p0 = acc[j][0] * invA, p1 = acc[j][1] * invA;
            float p2 = acc[j][2] * invB, p3 = acc[j][3] * invB;
            st_cs_f2(&attn_out[(abase + rA) * 64 + j * 8 + cb], p0, p1);
            st_cs_f2(&attn_out[(abase + rB) * 64 + j * 8 + cb], p2, p3);
            int tt = j >> 1, s = (j & 1) * 2;
            pa[tt][s + 0] = pack_h2(p0, p1);
            pa[tt][s + 1] = pack_h2(p2, p3);
        }

        float o[4][4];
        #pragma unroll
        for (int nj = 0; nj < 4; nj++)
            #pragma unroll
            for (int c = 0; c < 4; c++) o[nj][c] = 0.f;
        #pragma unroll
        for (int kc = 0; kc < 4; kc++) {
            #pragma unroll
            for (int vb = 0; vb < 2; vb++) {
                int ad = (kc * 16 + (lane & 15)) * SQ2 + hc + vb * 16 + (lane >> 4) * 8;
                uint32_t vh[4];
                ldsm4t(vh, sVh + ad);
                mma_f16(o[vb * 2],     pa[kc], vh);
                mma_f16(o[vb * 2 + 1], pa[kc], vh + 2);
            }
        }

        #pragma unroll
        for (int nj = 0; nj < 4; nj++) {
            int col = h * 32 + nj * 8 + cb;
            size_t gA = (size_t)(w * 64 + rA) * KD + col;
            size_t gB = (size_t)(w * 64 + rB) * KD + col;
            *(__half2*)&oh[gA] = __floats2half2_rn(o[nj][0], o[nj][1]);
            *(__half2*)&oh[gB] = __floats2half2_rn(o[nj][2], o[nj][3]);
        }
    }
}

// ------------------------------- launcher ----------------------------------
extern "C" void kernel_launch(void* const* d_in, const int* in_sizes, int n_in,
                              void* d_out, int out_size) {
    const float* q      = (const float*)d_in[0];
    const float* wq     = (const float*)d_in[1];
    const float* bq     = (const float*)d_in[2];
    const float* wkv    = (const float*)d_in[3];
    const float* bkv    = (const float*)d_in[4];
    const float* wproj  = (const float*)d_in[5];
    const float* bproj  = (const float*)d_in[6];
    const float* table  = (const float*)d_in[7];
    const int*   relidx = (const int*)d_in[8];

    float* out_x    = (float*)d_out;
    float* out_attn = out_x + (size_t)TOKENS * KD;

    __half *q_h, *w1_h, *w3_h, *qkv_h, *o_h;
    uint8_t* idx8;
    cudaGetSymbolAddress((void**)&q_h,   g_q_h);
    cudaGetSymbolAddress((void**)&w1_h,  g_w1_h);
    cudaGetSymbolAddress((void**)&w3_h,  g_w3_h);
    cudaGetSymbolAddress((void**)&qkv_h, g_qkv_h);
    cudaGetSymbolAddress((void**)&o_h,   g_o_h);
    cudaGetSymbolAddress((void**)&idx8,  g_idx8);

    const int smem_gemm = 3 * (128 * 40 + 32 * 136) * 2;             // 56,832
    const int smem_attn = 2 * 3 * 64 * 72 * 2 + 4 * 228 * 4 + 4096;  // 63,040
    cudaFuncSetAttribute(gemm_kernel<NC1, 1>, cudaFuncAttributeMaxDynamicSharedMemorySize, smem_gemm);
    cudaFuncSetAttribute(gemm_kernel<KD, 3>,  cudaFuncAttributeMaxDynamicSharedMemorySize, smem_gemm);
    cudaFuncSetAttribute(attn_mma_kernel, cudaFuncAttributeMaxDynamicSharedMemorySize, smem_attn);

    to_half4_kernel<<<(TOKENS * KD / 4 + 255) / 256, 256>>>(
        (const float4*)q, (uint2*)q_h, TOKENS * KD / 4);
    prep_weights_kernel<<<(KD * NC1) / 256, 256>>>(wq, wkv, wproj, relidx);

    gemm_kernel<NC1, 1><<<(TOKENS / 128) * (NC1 / 128), 128, smem_gemm>>>(
        q_h, w1_h, bq, bkv, qkv_h, nullptr);

    attn_mma_kernel<<<1024 * 4, 256, smem_attn>>>(
        qkv_h, table, idx8, out_attn, o_h);

    gemm_kernel<KD, 3><<<(TOKENS / 128) * (KD / 128), 128, smem_gemm>>>(
        o_h, w3_h, bproj, nullptr, nullptr, out_x);
}

// round 16
// speedup vs baseline: 1.0302x; 1.0254x over previous
#include <cuda_runtime.h>
#include <cuda_fp16.h>
#include <stdint.h>

#define TOKENS   65536
#define KD       512
#define NC1      1536
#define NHEADS   16
#define SCALE_Q  0.17677669529663688f

// ------------------------- device scratch (static) -------------------------
__device__ __half   g_q_h   [TOKENS * KD];
__device__ __half   g_w1_h  [KD * NC1];
__device__ __half   g_w3_h  [KD * KD];
__device__ __half   g_qkv_h [(size_t)TOKENS * NC1];
__device__ __half   g_o_h   [TOKENS * KD];
__device__ __half   g_bias16[NHEADS * 4096];      // [h][64*64] fp16 bias

// ------------------------------ PTX helpers --------------------------------
__device__ __forceinline__ uint32_t smem_u32(const void* p) {
    return (uint32_t)__cvta_generic_to_shared(p);
}
__device__ __forceinline__ void cp16(void* s, const void* g) {
    asm volatile("cp.async.cg.shared.global [%0], [%1], 16;\n"
                 :: "r"(smem_u32(s)), "l"(g));
}
__device__ __forceinline__ void cp_commit() { asm volatile("cp.async.commit_group;\n"); }
template<int N> __device__ __forceinline__ void cp_wait() {
    asm volatile("cp.async.wait_group %0;\n" :: "n"(N));
}
__device__ __forceinline__ void ldsm4(uint32_t r[4], const void* p) {
    asm volatile("ldmatrix.sync.aligned.m8n8.x4.shared.b16 {%0,%1,%2,%3}, [%4];\n"
        : "=r"(r[0]), "=r"(r[1]), "=r"(r[2]), "=r"(r[3]) : "r"(smem_u32(p)));
}
__device__ __forceinline__ void ldsm4t(uint32_t r[4], const void* p) {
    asm volatile("ldmatrix.sync.aligned.m8n8.x4.trans.shared.b16 {%0,%1,%2,%3}, [%4];\n"
        : "=r"(r[0]), "=r"(r[1]), "=r"(r[2]), "=r"(r[3]) : "r"(smem_u32(p)));
}
__device__ __forceinline__ void mma_f16(float c[4], const uint32_t a[4], const uint32_t b[2]) {
    asm volatile(
        "mma.sync.aligned.m16n8k16.row.col.f32.f16.f16.f32 "
        "{%0,%1,%2,%3}, {%4,%5,%6,%7}, {%8,%9}, {%0,%1,%2,%3};\n"
        : "+f"(c[0]), "+f"(c[1]), "+f"(c[2]), "+f"(c[3])
        : "r"(a[0]), "r"(a[1]), "r"(a[2]), "r"(a[3]), "r"(b[0]), "r"(b[1]));
}
__device__ __forceinline__ uint32_t pack_h2(float a, float b) {
    __half2 h = __floats2half2_rn(a, b);
    return *reinterpret_cast<uint32_t*>(&h);
}
__device__ __forceinline__ void st_cs_f2(float* p, float a, float b) {
    asm volatile("st.global.cs.v2.f32 [%0], {%1, %2};"
                 :: "l"(p), "f"(a), "f"(b) : "memory");
}

// ------------------------------ prep kernels -------------------------------
__global__ void to_half4_kernel(const float4* __restrict__ src,
                                uint2* __restrict__ dst, int n4) {
    int i = blockIdx.x * blockDim.x + threadIdx.x;
    if (i >= n4) return;
    float4 v = src[i];
    dst[i] = make_uint2(pack_h2(v.x, v.y), pack_h2(v.z, v.w));
}

// w1 (concat+convert), w3 (convert), bias16 (gather once) in one launch
__global__ void prep_weights_kernel(const float* __restrict__ wq,
                                    const float* __restrict__ wkv,
                                    const float* __restrict__ wproj,
                                    const float* __restrict__ table,
                                    const int* __restrict__ relidx) {
    int i = blockIdx.x * blockDim.x + threadIdx.x;
    if (i < KD * NC1) {
        int k = i / NC1, n = i - k * NC1;
        float v = (n < KD) ? wq[k * KD + n] : wkv[k * 1024 + (n - KD)];
        g_w1_h[i] = __float2half(v);
    }
    if (i < KD * KD) g_w3_h[i] = __float2half(wproj[i]);
    if (i < NHEADS * 4096) {
        int h = i >> 12, p = i & 4095;
        g_bias16[i] = __float2half(table[relidx[p] * NHEADS + h]);
    }
}

// ------ single-pass fp16 GEMM, 128x128x32 tiles, 4 warps @ m64n64 ----------
// (R12 configuration — best known, frozen.)  C = A_fp16 * B_fp16.
// MODE 1: QKV epilogue (bias + Q scale, fp16 out). MODE 3: fp32 out + bias.
template<int NCOLS, int MODE>
__global__ __launch_bounds__(128, 2)
void gemm_kernel(const __half* __restrict__ A, const __half* __restrict__ B,
                 const float* __restrict__ bias0, const float* __restrict__ bias1,
                 __half* __restrict__ outh, float* __restrict__ outf)
{
    constexpr int SA = 40;
    constexpr int SB = 136;
    constexpr int NB = NCOLS / 128;
    constexpr int GROUP_M = 16;
    constexpr int STAGE = 128 * SA + 32 * SB;   // 9472 halfs / stage
    constexpr int KITER = KD / 32;              // 16

    extern __shared__ char smem_raw[];
    __half* smem = (__half*)smem_raw;

    int bid = blockIdx.x;
    int gsz = GROUP_M * NB;
    int grp = bid / gsz;
    int rem = bid - grp * gsz;
    int bm  = grp * GROUP_M + (rem % GROUP_M);
    int bn  = rem / GROUP_M;

    int tid = threadIdx.x, lane = tid & 31, wid = tid >> 5;
    int wm = wid & 1, wn = wid >> 1;
    const int arow = tid >> 2, acol8 = (tid & 3) * 8;
    const int brow = tid >> 4, bcol8 = (tid & 15) * 8;

    auto load_stage = [&](__half* sb, int k0) {
        __half* dA = sb;
        __half* dB = sb + 128 * SA;
        #pragma unroll
        for (int i = 0; i < 4; i++) {
            size_t ga = (size_t)(bm * 128 + arow + 32 * i) * KD + k0 + acol8;
            cp16(dA + (arow + 32 * i) * SA + acol8, A + ga);
        }
        #pragma unroll
        for (int i = 0; i < 4; i++) {
            size_t gb = (size_t)(k0 + brow + 8 * i) * NCOLS + bn * 128 + bcol8;
            cp16(dB + (brow + 8 * i) * SB + bcol8, B + gb);
        }
    };

    float acc[4][8][4];
    #pragma unroll
    for (int a = 0; a < 4; a++)
        #pragma unroll
        for (int b = 0; b < 8; b++)
            #pragma unroll
            for (int c = 0; c < 4; c++) acc[a][b][c] = 0.f;

    __half* bc  = smem;
    __half* bnx = smem + STAGE;
    __half* blw = smem + 2 * STAGE;

    load_stage(bc, 0);
    cp_commit();
    load_stage(bnx, 32);
    cp_commit();

    #pragma unroll 1
    for (int kt = 0; kt < KITER; kt++) {
        cp_wait<1>();
        __syncthreads();
        if (kt + 2 < KITER) load_stage(blw, (kt + 2) * 32);
        cp_commit();

        const __half* cA = bc;
        const __half* cB = bc + 128 * SA;

        #pragma unroll
        for (int kk = 0; kk < 2; kk++) {
            uint32_t a[4][4], b[4][4];
            int ac = kk * 16 + (lane >> 4) * 8;
            int br = kk * 16 + (lane & 15);
            #pragma unroll
            for (int mt = 0; mt < 4; mt++) {
                int ar = wm * 64 + mt * 16 + (lane & 15);
                ldsm4(a[mt], cA + ar * SA + ac);
            }
            #pragma unroll
            for (int nj2 = 0; nj2 < 4; nj2++) {
                int bcc = wn * 64 + nj2 * 16 + (lane >> 4) * 8;
                ldsm4t(b[nj2], cB + br * SB + bcc);
            }
            #pragma unroll
            for (int nj2 = 0; nj2 < 4; nj2++) {
                #pragma unroll
                for (int t = 0; t < 2; t++) {
                    int nj = nj2 * 2 + t;
                    #pragma unroll
                    for (int mt = 0; mt < 4; mt++)
                        mma_f16(acc[mt][nj], a[mt], b[nj2] + 2 * t);
                }
            }
        }
        __half* tmp = bc;
        bc = bnx; bnx = blw; blw = tmp;
    }

    int row0 = bm * 128 + wm * 64 + (lane >> 2);
    int col0 = bn * 128 + wn * 64 + (lane & 3) * 2;
    #pragma unroll
    for (int mi = 0; mi < 4; mi++) {
        int ra = row0 + mi * 16;
        #pragma unroll
        for (int nj = 0; nj < 8; nj++) {
            int col = col0 + nj * 8;
            if (MODE == 1) {
                float b0, b1; float sc0, sc1;
                if (col < 512) { b0 = bias0[col]; b1 = bias0[col + 1]; sc0 = SCALE_Q; sc1 = SCALE_Q; }
                else { b0 = bias1[col - 512]; b1 = bias1[col - 511]; sc0 = 1.f; sc1 = 1.f; }
                size_t g0 = (size_t)ra * NCOLS + col;
                *(__half2*)&outh[g0] = __floats2half2_rn(
                    (acc[mi][nj][0] + b0) * sc0, (acc[mi][nj][1] + b1) * sc1);
                size_t g1 = (size_t)(ra + 8) * NCOLS + col;
                *(__half2*)&outh[g1] = __floats2half2_rn(
                    (acc[mi][nj][2] + b0) * sc0, (acc[mi][nj][3] + b1) * sc1);
            } else {
                float b0 = bias0[col], b1 = bias0[col + 1];
                st_cs_f2(&outf[(size_t)ra * NCOLS + col],
                         acc[mi][nj][0] + b0, acc[mi][nj][1] + b1);
                st_cs_f2(&outf[(size_t)(ra + 8) * NCOLS + col],
                         acc[mi][nj][2] + b0, acc[mi][nj][3] + b1);
            }
        }
    }
}

// ------------- tensor-core attention: 2 heads / CTA, 8 warps ---------------
// R13 single-tile shape; bias gather replaced by precomputed fp16 bias tiles
// loaded via cp.async into conflict-free (stride-72) smem and added with one
// half2 LDS per fragment pair.
__global__ __launch_bounds__(256)
void attn_mma_kernel(const __half* __restrict__ qkvh,
                     const __half* __restrict__ bias16,
                     float* __restrict__ attn_out,
                     __half* __restrict__ oh)
{
    constexpr int SQ2 = 72;                    // 64 + 8 pad (qkv tiles)
    constexpr int SBP = 72;                    // bias row stride (halfs)
    extern __shared__ char smraw[];
    __half* sT = (__half*)smraw;                       // 3 x [64*SQ2] : Q K V
    __half* sB = sT + 3 * (64 * SQ2);                  // 2 x [64*SBP] : bias h0,h1

    const int w = blockIdx.x >> 3, hp = blockIdx.x & 7;
    const int tid = threadIdx.x, lane = tid & 31, wid = tid >> 5;
    const int hsel = wid >> 2, wr = wid & 3;
    const int h = hp * 2 + hsel;
    const int hc = hsel * 32;
    const size_t rowbase = (size_t)(w * 64) * NC1;

    // qkv tiles: region a=0(Q)/1(K)/2(V); each row = 64 halfs = 8 cp16
    #pragma unroll
    for (int it = 0; it < 6; it++) {
        int e = tid + it * 256;
        int a = e >> 9;
        int rem = e & 511;
        int row = rem >> 3, c = (rem & 7) * 8;
        size_t g = rowbase + (size_t)row * NC1 + hp * 64 + a * 512 + c;
        cp16(sT + a * (64 * SQ2) + row * SQ2 + c, qkvh + g);
    }
    // bias tiles: 2 heads x 64 rows x 8 cp16 = 1024 cp16
    #pragma unroll
    for (int it = 0; it < 4; it++) {
        int e = tid + it * 256;
        int hd = e >> 9;
        int rem = e & 511;
        int row = rem >> 3, c = (rem & 7) * 8;
        cp16(sB + hd * (64 * SBP) + row * SBP + c,
             bias16 + (hp * 2 + hd) * 4096 + row * 64 + c);
    }
    cp_commit();
    cp_wait<0>();
    __syncthreads();

    const __half* sQh = sT;
    const __half* sKh = sT + 1 * (64 * SQ2);
    const __half* sVh = sT + 2 * (64 * SQ2);
    const __half* sBh = sB + hsel * (64 * SBP);

    const int r0 = wr * 16;

    uint32_t qa[2][4];
    #pragma unroll
    for (int kc = 0; kc < 2; kc++) {
        int ad = (r0 + (lane & 15)) * SQ2 + hc + kc * 16 + (lane >> 4) * 8;
        ldsm4(qa[kc], sQh + ad);
    }
    float acc[8][4];
    #pragma unroll
    for (int j = 0; j < 8; j++)
        #pragma unroll
        for (int c = 0; c < 4; c++) acc[j][c] = 0.f;

    #pragma unroll
    for (int kc = 0; kc < 2; kc++) {
        #pragma unroll
        for (int jj = 0; jj < 4; jj++) {
            int row = jj * 16 + (lane & 7) + ((lane >> 4) & 1) * 8;
            int col = hc + kc * 16 + ((lane >> 3) & 1) * 8;
            uint32_t kh[4];
            ldsm4(kh, sKh + row * SQ2 + col);
            mma_f16(acc[2 * jj],     qa[kc], kh);
            mma_f16(acc[2 * jj + 1], qa[kc], kh + 2);
        }
    }

    const int rA = r0 + (lane >> 2), rB = rA + 8;
    const int cb = (lane & 3) * 2;
    float mA = -1e30f, mB = -1e30f;
    #pragma unroll
    for (int j = 0; j < 8; j++) {
        int c0 = j * 8 + cb;
        float2 fA = __half22float2(*(const __half2*)&sBh[rA * SBP + c0]);
        float2 fB = __half22float2(*(const __half2*)&sBh[rB * SBP + c0]);
        acc[j][0] += fA.x;
        acc[j][1] += fA.y;
        acc[j][2] += fB.x;
        acc[j][3] += fB.y;
        mA = fmaxf(mA, fmaxf(acc[j][0], acc[j][1]));
        mB = fmaxf(mB, fmaxf(acc[j][2], acc[j][3]));
    }
    mA = fmaxf(mA, __shfl_xor_sync(0xffffffffu, mA, 1));
    mA = fmaxf(mA, __shfl_xor_sync(0xffffffffu, mA, 2));
    mB = fmaxf(mB, __shfl_xor_sync(0xffffffffu, mB, 1));
    mB = fmaxf(mB, __shfl_xor_sync(0xffffffffu, mB, 2));
    float sA = 0.f, sB2 = 0.f;
    #pragma unroll
    for (int j = 0; j < 8; j++) {
        acc[j][0] = __expf(acc[j][0] - mA);
        acc[j][1] = __expf(acc[j][1] - mA);
        acc[j][2] = __expf(acc[j][2] - mB);
        acc[j][3] = __expf(acc[j][3] - mB);
        sA  += acc[j][0] + acc[j][1];
        sB2 += acc[j][2] + acc[j][3];
    }
    sA  += __shfl_xor_sync(0xffffffffu, sA, 1);
    sA  += __shfl_xor_sync(0xffffffffu, sA, 2);
    sB2 += __shfl_xor_sync(0xffffffffu, sB2, 1);
    sB2 += __shfl_xor_sync(0xffffffffu, sB2, 2);
    const float invA = 1.f / sA, invB = 1.f / sB2;

    uint32_t pa[4][4];
    const size_t abase = ((size_t)w * NHEADS + h) * 64;
    #pragma unroll
    for (int j = 0; j < 8; j++) {
        float p0 = acc[j][0] * invA, p1 = acc[j][1] * invA;
        float p2 = acc[j][2] * invB, p3 = acc[j][3] * invB;
        st_cs_f2(&attn_out[(abase + rA) * 64 + j * 8 + cb], p0, p1);
        st_cs_f2(&attn_out[(abase + rB) * 64 + j * 8 + cb], p2, p3);
        int t = j >> 1, s = (j & 1) * 2;
        pa[t][s + 0] = pack_h2(p0, p1);
        pa[t][s + 1] = pack_h2(p2, p3);
    }

    float o[4][4];
    #pragma unroll
    for (int nj = 0; nj < 4; nj++)
        #pragma unroll
        for (int c = 0; c < 4; c++) o[nj][c] = 0.f;
    #pragma unroll
    for (int kc = 0; kc < 4; kc++) {
        #pragma unroll
        for (int vb = 0; vb < 2; vb++) {
            int ad = (kc * 16 + (lane & 15)) * SQ2 + hc + vb * 16 + (lane >> 4) * 8;
            uint32_t vh[4];
            ldsm4t(vh, sVh + ad);
            mma_f16(o[vb * 2],     pa[kc], vh);
            mma_f16(o[vb * 2 + 1], pa[kc], vh + 2);
        }
    }

    #pragma unroll
    for (int nj = 0; nj < 4; nj++) {
        int col = h * 32 + nj * 8 + cb;
        size_t gA = (size_t)(w * 64 + rA) * KD + col;
        size_t gB = (size_t)(w * 64 + rB) * KD + col;
        *(__half2*)&oh[gA] = __floats2half2_rn(o[nj][0], o[nj][1]);
        *(__half2*)&oh[gB] = __floats2half2_rn(o[nj][2], o[nj][3]);
    }
}

// ------------------------------- launcher ----------------------------------
extern "C" void kernel_launch(void* const* d_in, const int* in_sizes, int n_in,
                              void* d_out, int out_size) {
    const float* q      = (const float*)d_in[0];
    const float* wq     = (const float*)d_in[1];
    const float* bq     = (const float*)d_in[2];
    const float* wkv    = (const float*)d_in[3];
    const float* bkv    = (const float*)d_in[4];
    const float* wproj  = (const float*)d_in[5];
    const float* bproj  = (const float*)d_in[6];
    const float* table  = (const float*)d_in[7];
    const int*   relidx = (const int*)d_in[8];

    float* out_x    = (float*)d_out;
    float* out_attn = out_x + (size_t)TOKENS * KD;

    __half *q_h, *w1_h, *w3_h, *qkv_h, *o_h, *bias16;
    cudaGetSymbolAddress((void**)&q_h,    g_q_h);
    cudaGetSymbolAddress((void**)&w1_h,   g_w1_h);
    cudaGetSymbolAddress((void**)&w3_h,   g_w3_h);
    cudaGetSymbolAddress((void**)&qkv_h,  g_qkv_h);
    cudaGetSymbolAddress((void**)&o_h,    g_o_h);
    cudaGetSymbolAddress((void**)&bias16, g_bias16);

    const int smem_gemm = 3 * (128 * 40 + 32 * 136) * 2;          // 56,832
    const int smem_attn = (3 * 64 * 72 + 2 * 64 * 72) * 2;        // 46,080
    cudaFuncSetAttribute(gemm_kernel<NC1, 1>, cudaFuncAttributeMaxDynamicSharedMemorySize, smem_gemm);
    cudaFuncSetAttribute(gemm_kernel<KD, 3>,  cudaFuncAttributeMaxDynamicSharedMemorySize, smem_gemm);
    cudaFuncSetAttribute(attn_mma_kernel, cudaFuncAttributeMaxDynamicSharedMemorySize, smem_attn);

    to_half4_kernel<<<(TOKENS * KD / 4 + 255) / 256, 256>>>(
        (const float4*)q, (uint2*)q_h, TOKENS * KD / 4);
    prep_weights_kernel<<<(KD * NC1) / 256, 256>>>(wq, wkv, wproj, table, relidx);

    gemm_kernel<NC1, 1><<<(TOKENS / 128) * (NC1 / 128), 128, smem_gemm>>>(
        q_h, w1_h, bq, bkv, qkv_h, nullptr);

    attn_mma_kernel<<<1024 * 8, 256, smem_attn>>>(
        qkv_h, bias16, out_attn, o_h);

    gemm_kernel<KD, 3><<<(TOKENS / 128) * (KD / 128), 128, smem_gemm>>>(
        o_h, w3_h, bproj, nullptr, nullptr, out_x);
}